// round 4
// baseline (speedup 1.0000x reference)
#include <cuda_runtime.h>

#define NMAX 100000
#define EMAX 1600000
#define HID 64

// scratch (no cudaMalloc allowed)
__device__ __align__(16) float g_xp [NMAX * HID];
__device__ __align__(16) float g_h  [NMAX * HID];
__device__ float g_als[NMAX * 2];
__device__ float g_ald[NMAX * 2];
__device__ int   g_cnt[NMAX];
__device__ int   g_off[NMAX + 1];
__device__ int   g_cur[NMAX];
__device__ int   g_srcs[EMAX];
__device__ int   g_is64;

// ---------------------------------------------------------------------------
// Detect whether edge_index is stored as int64 (high 32-bit words all zero)
// or int32. Checks the first 2048 odd words.
// ---------------------------------------------------------------------------
__global__ __launch_bounds__(256)
void detect_kernel(const int* __restrict__ ei)
{
    __shared__ int s_or;
    if (threadIdx.x == 0) s_or = 0;
    __syncthreads();
    int o = 0;
    for (int i = threadIdx.x; i < 2048; i += 256)
        o |= ei[2 * i + 1];
    if (o) atomicOr(&s_or, 1);
    __syncthreads();
    if (threadIdx.x == 0) g_is64 = (s_or == 0) ? 1 : 0;
}

__device__ __forceinline__ int load_src(const int* ei, int E, int i, int is64)
{
    return is64 ? ei[2 * i] : ei[i];
}
__device__ __forceinline__ int load_dst(const int* ei, int E, int i, int is64)
{
    return is64 ? ei[2 * E + 2 * i] : ei[E + i];
}

// ---------------------------------------------------------------------------
// CSR build (by destination). Only integer atomics.
// ---------------------------------------------------------------------------
__global__ __launch_bounds__(256)
void zero_cnt_kernel(int n)
{
    int i = blockIdx.x * blockDim.x + threadIdx.x;
    if (i < n) g_cnt[i] = 0;
}

__global__ __launch_bounds__(256)
void hist_kernel(const int* __restrict__ ei, int E)
{
    int i = blockIdx.x * blockDim.x + threadIdx.x;
    int is64 = g_is64;
    if (i < E) atomicAdd(&g_cnt[load_dst(ei, E, i, is64)], 1);
}

// single-block exclusive scan over g_cnt -> g_off, g_cur; g_off[n] = E
__global__ __launch_bounds__(1024)
void scan_kernel(int n, int E)
{
    __shared__ int ps[1024];
    const int t = threadIdx.x;
    const int chunk = (n + 1023) >> 10;
    const int lo = t * chunk;
    const int hi = min(lo + chunk, n);

    int s = 0;
    for (int i = lo; i < hi; i++) s += g_cnt[i];
    ps[t] = s;
    __syncthreads();
    for (int off = 1; off < 1024; off <<= 1) {
        int v = (t >= off) ? ps[t - off] : 0;
        __syncthreads();
        ps[t] += v;
        __syncthreads();
    }
    int run = ps[t] - s;   // exclusive prefix
    for (int i = lo; i < hi; i++) {
        g_off[i] = run;
        g_cur[i] = run;
        run += g_cnt[i];
    }
    if (t == 1023) g_off[n] = E;
}

__global__ __launch_bounds__(256)
void scatter_kernel(const int* __restrict__ ei, int E)
{
    int i = blockIdx.x * blockDim.x + threadIdx.x;
    if (i >= E) return;
    int is64 = g_is64;
    int d = load_dst(ei, E, i, is64);
    int s = load_src(ei, E, i, is64);
    int pos = atomicAdd(&g_cur[d], 1);
    g_srcs[pos] = s;
}

// ---------------------------------------------------------------------------
// Fused GEMM + attention-logit epilogue.
//   xp = X @ W  (X:[n,K], W:[K,64])  -> g_xp
//   al_src[n,h] = <xp[n,h,:], att_s[h,:]>  -> g_als ; al_dst likewise -> g_ald
// Block: 256 thr, tile 64 rows x 64 cols, thread tile 4x4, K chunked by 64.
// ---------------------------------------------------------------------------
template<int K, bool FIRST>
__global__ __launch_bounds__(256)
void gemm_al_kernel(const float* __restrict__ Xin,
                    const float* __restrict__ W,
                    const float* __restrict__ att_s,
                    const float* __restrict__ att_d,
                    int n)
{
    const float* __restrict__ X = FIRST ? Xin : g_h;

    __shared__ float sW[64 * 64];
    __shared__ float sXT[64][65];

    const int tid = threadIdx.x;
    const int cx  = tid & 15;           // col group (4 cols)
    const int ry  = tid >> 4;           // row group (4 rows)
    const int row0 = blockIdx.x * 64;

    float C[4][4];
#pragma unroll
    for (int i = 0; i < 4; i++)
#pragma unroll
        for (int j = 0; j < 4; j++) C[i][j] = 0.f;

    for (int kc = 0; kc < K; kc += 64) {
        __syncthreads();
#pragma unroll
        for (int q = 0; q < 4; q++) {
            int idx4 = tid + q * 256;
            float4 v = *(const float4*)&W[kc * 64 + idx4 * 4];
            *(float4*)&sW[idx4 * 4] = v;
        }
#pragma unroll
        for (int q = 0; q < 4; q++) {
            int lin = tid + q * 256;
            int r  = lin >> 4;
            int c4 = lin & 15;
            int gr = row0 + r; if (gr > n - 1) gr = n - 1;
            float4 v = *(const float4*)&X[(long long)gr * K + kc + c4 * 4];
            sXT[c4 * 4 + 0][r] = v.x;
            sXT[c4 * 4 + 1][r] = v.y;
            sXT[c4 * 4 + 2][r] = v.z;
            sXT[c4 * 4 + 3][r] = v.w;
        }
        __syncthreads();
#pragma unroll
        for (int k = 0; k < 64; k++) {
            float4 wv = *(const float4*)&sW[k * 64 + cx * 4];
            float xr[4];
#pragma unroll
            for (int i = 0; i < 4; i++) xr[i] = sXT[k][ry * 4 + i];
#pragma unroll
            for (int i = 0; i < 4; i++) {
                C[i][0] = fmaf(xr[i], wv.x, C[i][0]);
                C[i][1] = fmaf(xr[i], wv.y, C[i][1]);
                C[i][2] = fmaf(xr[i], wv.z, C[i][2]);
                C[i][3] = fmaf(xr[i], wv.w, C[i][3]);
            }
        }
    }

    // epilogue: attention logits
    const int h    = cx >> 3;
    const int lane = tid & 31;
    float asv[4], adv[4];
#pragma unroll
    for (int j = 0; j < 4; j++) {
        asv[j] = __ldg(&att_s[cx * 4 + j]);
        adv[j] = __ldg(&att_d[cx * 4 + j]);
    }

#pragma unroll
    for (int i = 0; i < 4; i++) {
        float als = 0.f, ald = 0.f;
#pragma unroll
        for (int j = 0; j < 4; j++) {
            als = fmaf(C[i][j], asv[j], als);
            ald = fmaf(C[i][j], adv[j], ald);
        }
#pragma unroll
        for (int off = 4; off; off >>= 1) {
            als += __shfl_down_sync(0xffffffffu, als, off, 8);
            ald += __shfl_down_sync(0xffffffffu, ald, off, 8);
        }
        int row = row0 + ry * 4 + i;
        if (row < n) {
            if ((lane & 7) == 0) {
                g_als[row * 2 + h] = als;
                g_ald[row * 2 + h] = ald;
            }
            float4 xv = make_float4(C[i][0], C[i][1], C[i][2], C[i][3]);
            *(float4*)&g_xp[row * HID + cx * 4] = xv;
        }
    }
}

// ---------------------------------------------------------------------------
// Gather pass: one warp per destination node. No float atomics.
//   w_e = exp(lrelu(als[s]+ald[d])) ; acc += xp[s]*w ; seg += w
// Self-loop folded into init. Finish: acc/seg + bias (+ELU for layer 1).
// ---------------------------------------------------------------------------
template<bool LAST>
__global__ __launch_bounds__(256)
void gather_kernel(const float* __restrict__ bias,
                   float* __restrict__ out, int n)
{
    int warp = (blockIdx.x * 256 + threadIdx.x) >> 5;
    int lane = threadIdx.x & 31;
    if (warp >= n) return;
    const int node = warp;
    const int h = lane >> 4;            // lanes 0-15: head 0, 16-31: head 1

    const float ald_h = __ldg(&g_ald[node * 2 + h]);

    // self loop
    float t0 = __ldg(&g_als[node * 2 + h]) + ald_h;
    t0 = fmaxf(t0, 0.2f * t0);
    float w = __expf(t0);
    float2 xv = *(const float2*)&g_xp[node * HID + lane * 2];
    float a0 = xv.x * w, a1 = xv.y * w, seg = w;

    const int beg = g_off[node];
    const int end = g_off[node + 1];
    for (int i = beg; i < end; i += 32) {
        int cnt = min(32, end - i);
        int sidx = (i + lane < end) ? __ldg(&g_srcs[i + lane]) : 0;
#pragma unroll 4
        for (int j = 0; j < cnt; j++) {
            int s = __shfl_sync(0xffffffffu, sidx, j);
            float tt = __ldg(&g_als[s * 2 + h]) + ald_h;
            tt = fmaxf(tt, 0.2f * tt);
            float ww = __expf(tt);
            float2 xs = *(const float2*)&g_xp[s * HID + lane * 2];
            a0 = fmaf(xs.x, ww, a0);
            a1 = fmaf(xs.y, ww, a1);
            seg += ww;
        }
    }

    float inv = 1.f / (seg + 1e-16f);
    float2 bv = *(const float2*)&bias[lane * 2];
    float v0 = a0 * inv + bv.x;
    float v1 = a1 * inv + bv.y;
    if (!LAST) {
        v0 = v0 > 0.f ? v0 : expm1f(v0);
        v1 = v1 > 0.f ? v1 : expm1f(v1);
        *(float2*)&g_h[node * HID + lane * 2] = make_float2(v0, v1);
    } else {
        *(float2*)&out[node * HID + lane * 2] = make_float2(v0, v1);
    }
}

extern "C" void kernel_launch(void* const* d_in, const int* in_sizes, int n_in,
                              void* d_out, int out_size)
{
    const float* x   = (const float*)d_in[0];
    const int*   ei  = (const int*)d_in[1];
    const float* W1  = (const float*)d_in[2];
    const float* as1 = (const float*)d_in[3];
    const float* ad1 = (const float*)d_in[4];
    const float* b1  = (const float*)d_in[5];
    const float* W2  = (const float*)d_in[6];
    const float* as2 = (const float*)d_in[7];
    const float* ad2 = (const float*)d_in[8];
    const float* b2  = (const float*)d_in[9];

    const int n = in_sizes[0] / 128;          // 100000
    const int E = in_sizes[1] / 2;            // 1600000 (elements are 2E either way)
    const int gb  = (n + 63) / 64;
    const int nbl = (n + 255) / 256;
    const int ebl = (E + 255) / 256;
    const int wbl = ((n * 32) + 255) / 256;   // warp per node

    // CSR build (graph is shared by both layers)
    detect_kernel<<<1, 256>>>(ei);
    zero_cnt_kernel<<<nbl, 256>>>(n);
    hist_kernel<<<ebl, 256>>>(ei, E);
    scan_kernel<<<1, 1024>>>(n, E);
    scatter_kernel<<<ebl, 256>>>(ei, E);

    // layer 1
    gemm_al_kernel<128, true><<<gb, 256>>>(x, W1, as1, ad1, n);
    gather_kernel<false><<<wbl, 256>>>(b1, nullptr, n);
    // layer 2
    gemm_al_kernel<64, false><<<gb, 256>>>(x, W2, as2, ad2, n);
    gather_kernel<true><<<wbl, 256>>>(b2, (float*)d_out, n);
}

// round 5
// speedup vs baseline: 1.6203x; 1.6203x over previous
#include <cuda_runtime.h>

#define NMAX 100000
#define EMAX 1600000
#define HID 64
#define SCAN_CHUNK 1024   // elements per scan block (256 thr * 4)

// scratch (no cudaMalloc allowed)
__device__ __align__(16) float g_xp [NMAX * HID];
__device__ __align__(16) float g_h  [NMAX * HID];
__device__ float g_als[NMAX * 2];
__device__ float g_ald[NMAX * 2];
__device__ int   g_cnt[NMAX];
__device__ int   g_off[NMAX + 1];
__device__ int   g_cur[NMAX];
__device__ int   g_srcs[EMAX];
__device__ int   g_bsums[(NMAX + SCAN_CHUNK - 1) / SCAN_CHUNK];
__device__ int   g_boff [(NMAX + SCAN_CHUNK - 1) / SCAN_CHUNK];
__device__ int   g_is64;

// ---------------------------------------------------------------------------
// Detect whether edge_index is stored as int64 (high 32-bit words all zero)
// or int32. Checks the first 2048 odd words.
// ---------------------------------------------------------------------------
__global__ __launch_bounds__(256)
void detect_kernel(const int* __restrict__ ei)
{
    __shared__ int s_or;
    if (threadIdx.x == 0) s_or = 0;
    __syncthreads();
    int o = 0;
    for (int i = threadIdx.x; i < 2048; i += 256)
        o |= ei[2 * i + 1];
    if (o) atomicOr(&s_or, 1);
    __syncthreads();
    if (threadIdx.x == 0) g_is64 = (s_or == 0) ? 1 : 0;
}

__device__ __forceinline__ int load_src(const int* ei, int E, int i, int is64)
{
    return is64 ? ei[2 * i] : ei[i];
}
__device__ __forceinline__ int load_dst(const int* ei, int E, int i, int is64)
{
    return is64 ? ei[2 * E + 2 * i] : ei[E + i];
}

// ---------------------------------------------------------------------------
// CSR build (by destination). Only integer atomics.
// ---------------------------------------------------------------------------
__global__ __launch_bounds__(256)
void zero_cnt_kernel(int n)
{
    int i = blockIdx.x * blockDim.x + threadIdx.x;
    if (i < n) g_cnt[i] = 0;
}

__global__ __launch_bounds__(256)
void hist_kernel(const int* __restrict__ ei, int E)
{
    int i = blockIdx.x * blockDim.x + threadIdx.x;
    int is64 = g_is64;
    if (i < E) atomicAdd(&g_cnt[load_dst(ei, E, i, is64)], 1);
}

// ---------------------------------------------------------------------------
// 3-phase parallel exclusive scan over g_cnt[0..n) -> g_off/g_cur, g_off[n]=E
// ---------------------------------------------------------------------------
__device__ __forceinline__ int block_exscan256(int v, int* sh)
{
    // returns exclusive prefix of v across 256 threads; sh = 256 ints
    const int t = threadIdx.x;
    sh[t] = v;
    __syncthreads();
#pragma unroll
    for (int off = 1; off < 256; off <<= 1) {
        int u = (t >= off) ? sh[t - off] : 0;
        __syncthreads();
        sh[t] += u;
        __syncthreads();
    }
    return sh[t] - v;
}

__global__ __launch_bounds__(256)
void scan_partial(int n)
{
    __shared__ int sh[256];
    const int t = threadIdx.x;
    const int base = blockIdx.x * SCAN_CHUNK + t * 4;
    int s = 0;
#pragma unroll
    for (int j = 0; j < 4; j++)
        if (base + j < n) s += g_cnt[base + j];
    sh[t] = s;
    __syncthreads();
    for (int off = 128; off; off >>= 1) {
        if (t < off) sh[t] += sh[t + off];
        __syncthreads();
    }
    if (t == 0) g_bsums[blockIdx.x] = sh[0];
}

__global__ __launch_bounds__(256)
void scan_bsums(int nb)
{
    __shared__ int sh[256];
    const int t = threadIdx.x;
    int v = (t < nb) ? g_bsums[t] : 0;
    int ex = block_exscan256(v, sh);
    if (t < nb) g_boff[t] = ex;
}

__global__ __launch_bounds__(256)
void scan_final(int n, int E)
{
    __shared__ int sh[256];
    const int t = threadIdx.x;
    const int base = blockIdx.x * SCAN_CHUNK + t * 4;
    int c[4];
    int s = 0;
#pragma unroll
    for (int j = 0; j < 4; j++) {
        c[j] = (base + j < n) ? g_cnt[base + j] : 0;
        s += c[j];
    }
    int ex = block_exscan256(s, sh) + g_boff[blockIdx.x];
#pragma unroll
    for (int j = 0; j < 4; j++) {
        if (base + j < n) {
            g_off[base + j] = ex;
            g_cur[base + j] = ex;
        }
        ex += c[j];
    }
    if (blockIdx.x == 0 && t == 0) g_off[n] = E;
}

__global__ __launch_bounds__(256)
void scatter_kernel(const int* __restrict__ ei, int E)
{
    int i = blockIdx.x * blockDim.x + threadIdx.x;
    if (i >= E) return;
    int is64 = g_is64;
    int d = load_dst(ei, E, i, is64);
    int s = load_src(ei, E, i, is64);
    int pos = atomicAdd(&g_cur[d], 1);
    g_srcs[pos] = s;
}

// ---------------------------------------------------------------------------
// Fused GEMM + attention-logit epilogue.
//   xp = X @ W  (X:[n,K], W:[K,64])  -> g_xp
//   al_src[n,h] = <xp[n,h,:], att_s[h,:]>  -> g_als ; al_dst likewise -> g_ald
// Block: 256 thr, tile 64 rows x 64 cols, thread tile 4x4, K chunked by 64.
// ---------------------------------------------------------------------------
template<int K, bool FIRST>
__global__ __launch_bounds__(256)
void gemm_al_kernel(const float* __restrict__ Xin,
                    const float* __restrict__ W,
                    const float* __restrict__ att_s,
                    const float* __restrict__ att_d,
                    int n)
{
    const float* __restrict__ X = FIRST ? Xin : g_h;

    __shared__ float sW[64 * 64];
    __shared__ float sXT[64][65];

    const int tid = threadIdx.x;
    const int cx  = tid & 15;           // col group (4 cols)
    const int ry  = tid >> 4;           // row group (4 rows)
    const int row0 = blockIdx.x * 64;

    float C[4][4];
#pragma unroll
    for (int i = 0; i < 4; i++)
#pragma unroll
        for (int j = 0; j < 4; j++) C[i][j] = 0.f;

    for (int kc = 0; kc < K; kc += 64) {
        __syncthreads();
#pragma unroll
        for (int q = 0; q < 4; q++) {
            int idx4 = tid + q * 256;
            float4 v = *(const float4*)&W[kc * 64 + idx4 * 4];
            *(float4*)&sW[idx4 * 4] = v;
        }
#pragma unroll
        for (int q = 0; q < 4; q++) {
            int lin = tid + q * 256;
            int r  = lin >> 4;
            int c4 = lin & 15;
            int gr = row0 + r; if (gr > n - 1) gr = n - 1;
            float4 v = *(const float4*)&X[(long long)gr * K + kc + c4 * 4];
            sXT[c4 * 4 + 0][r] = v.x;
            sXT[c4 * 4 + 1][r] = v.y;
            sXT[c4 * 4 + 2][r] = v.z;
            sXT[c4 * 4 + 3][r] = v.w;
        }
        __syncthreads();
#pragma unroll
        for (int k = 0; k < 64; k++) {
            float4 wv = *(const float4*)&sW[k * 64 + cx * 4];
            float xr[4];
#pragma unroll
            for (int i = 0; i < 4; i++) xr[i] = sXT[k][ry * 4 + i];
#pragma unroll
            for (int i = 0; i < 4; i++) {
                C[i][0] = fmaf(xr[i], wv.x, C[i][0]);
                C[i][1] = fmaf(xr[i], wv.y, C[i][1]);
                C[i][2] = fmaf(xr[i], wv.z, C[i][2]);
                C[i][3] = fmaf(xr[i], wv.w, C[i][3]);
            }
        }
    }

    // epilogue: attention logits
    const int h    = cx >> 3;
    const int lane = tid & 31;
    float asv[4], adv[4];
#pragma unroll
    for (int j = 0; j < 4; j++) {
        asv[j] = __ldg(&att_s[cx * 4 + j]);
        adv[j] = __ldg(&att_d[cx * 4 + j]);
    }

#pragma unroll
    for (int i = 0; i < 4; i++) {
        float als = 0.f, ald = 0.f;
#pragma unroll
        for (int j = 0; j < 4; j++) {
            als = fmaf(C[i][j], asv[j], als);
            ald = fmaf(C[i][j], adv[j], ald);
        }
#pragma unroll
        for (int off = 4; off; off >>= 1) {
            als += __shfl_down_sync(0xffffffffu, als, off, 8);
            ald += __shfl_down_sync(0xffffffffu, ald, off, 8);
        }
        int row = row0 + ry * 4 + i;
        if (row < n) {
            if ((lane & 7) == 0) {
                g_als[row * 2 + h] = als;
                g_ald[row * 2 + h] = ald;
            }
            float4 xv = make_float4(C[i][0], C[i][1], C[i][2], C[i][3]);
            *(float4*)&g_xp[row * HID + cx * 4] = xv;
        }
    }
}

// ---------------------------------------------------------------------------
// Gather pass: one warp per destination node. No float atomics.
//   w_e = exp(lrelu(als[s]+ald[d])) ; acc += xp[s]*w ; seg += w
// Self-loop folded into init. Finish: acc/seg + bias (+ELU for layer 1).
// ---------------------------------------------------------------------------
template<bool LAST>
__global__ __launch_bounds__(256)
void gather_kernel(const float* __restrict__ bias,
                   float* __restrict__ out, int n)
{
    int warp = (blockIdx.x * 256 + threadIdx.x) >> 5;
    int lane = threadIdx.x & 31;
    if (warp >= n) return;
    const int node = warp;
    const int h = lane >> 4;            // lanes 0-15: head 0, 16-31: head 1

    const float ald_h = __ldg(&g_ald[node * 2 + h]);

    // self loop
    float t0 = __ldg(&g_als[node * 2 + h]) + ald_h;
    t0 = fmaxf(t0, 0.2f * t0);
    float w = __expf(t0);
    float2 xv = *(const float2*)&g_xp[node * HID + lane * 2];
    float a0 = xv.x * w, a1 = xv.y * w, seg = w;

    const int beg = g_off[node];
    const int end = g_off[node + 1];
    for (int i = beg; i < end; i += 32) {
        int cnt = min(32, end - i);
        int sidx = (i + lane < end) ? __ldg(&g_srcs[i + lane]) : 0;
#pragma unroll 4
        for (int j = 0; j < cnt; j++) {
            int s = __shfl_sync(0xffffffffu, sidx, j);
            float tt = __ldg(&g_als[s * 2 + h]) + ald_h;
            tt = fmaxf(tt, 0.2f * tt);
            float ww = __expf(tt);
            float2 xs = *(const float2*)&g_xp[s * HID + lane * 2];
            a0 = fmaf(xs.x, ww, a0);
            a1 = fmaf(xs.y, ww, a1);
            seg += ww;
        }
    }

    float inv = 1.f / (seg + 1e-16f);
    float2 bv = *(const float2*)&bias[lane * 2];
    float v0 = a0 * inv + bv.x;
    float v1 = a1 * inv + bv.y;
    if (!LAST) {
        v0 = v0 > 0.f ? v0 : expm1f(v0);
        v1 = v1 > 0.f ? v1 : expm1f(v1);
        *(float2*)&g_h[node * HID + lane * 2] = make_float2(v0, v1);
    } else {
        *(float2*)&out[node * HID + lane * 2] = make_float2(v0, v1);
    }
}

extern "C" void kernel_launch(void* const* d_in, const int* in_sizes, int n_in,
                              void* d_out, int out_size)
{
    const float* x   = (const float*)d_in[0];
    const int*   ei  = (const int*)d_in[1];
    const float* W1  = (const float*)d_in[2];
    const float* as1 = (const float*)d_in[3];
    const float* ad1 = (const float*)d_in[4];
    const float* b1  = (const float*)d_in[5];
    const float* W2  = (const float*)d_in[6];
    const float* as2 = (const float*)d_in[7];
    const float* ad2 = (const float*)d_in[8];
    const float* b2  = (const float*)d_in[9];

    const int n = in_sizes[0] / 128;          // 100000
    const int E = in_sizes[1] / 2;            // 1600000
    const int gb  = (n + 63) / 64;
    const int nbl = (n + 255) / 256;
    const int ebl = (E + 255) / 256;
    const int wbl = ((n * 32) + 255) / 256;   // warp per node
    const int sb  = (n + SCAN_CHUNK - 1) / SCAN_CHUNK;

    // CSR build (graph is shared by both layers)
    detect_kernel<<<1, 256>>>(ei);
    zero_cnt_kernel<<<nbl, 256>>>(n);
    hist_kernel<<<ebl, 256>>>(ei, E);
    scan_partial<<<sb, 256>>>(n);
    scan_bsums<<<1, 256>>>(sb);
    scan_final<<<sb, 256>>>(n, E);
    scatter_kernel<<<ebl, 256>>>(ei, E);

    // layer 1
    gemm_al_kernel<128, true><<<gb, 256>>>(x, W1, as1, ad1, n);
    gather_kernel<false><<<wbl, 256>>>(b1, nullptr, n);
    // layer 2
    gemm_al_kernel<64, false><<<gb, 256>>>(x, W2, as2, ad2, n);
    gather_kernel<true><<<wbl, 256>>>(b2, (float*)d_out, n);
}